// round 14
// baseline (speedup 1.0000x reference)
#include <cuda_runtime.h>
#include <cuda_fp16.h>
#include <math.h>
#include <stdint.h>

// Problem shape
#define BATCH 32
#define LDIM  512
#define DDIM  768
#define EPSF  1e-5f

// Gram tiling: 128(m) x 64(n) tiles on the 6x12 grid, cover tj >= 2*ti -> 42 tiles.
#define NTILES  42
#define BK      32                   // k (halfs) per stage = 64B rows
#define NCHUNK  (LDIM / BK)          // 16
#define STAGES  4
#define A_BYTES (128 * BK * 2)       // 8192
#define B_BYTES (64  * BK * 2)       // 4096
#define STAGE_BYTES (A_BYTES + B_BYTES)          // 12288
#define SMEM_BYTES  (STAGES * STAGE_BYTES)       // 49152

// Prep smem: 32 rows x 769 floats (odd pad -> conflict-free transpose) + 32 w's
#define PPAD 769
#define PREP_SMEM ((32 * PPAD + 32) * 4)         // 98560

// Scratch: transposed, weight-folded fp16 copy  Zh[b][d][l]  (24 MB)
__device__ __align__(16) __half g_Zh[BATCH * DDIM * LDIM];

__device__ __forceinline__ void cp16(uint32_t saddr, const void* g) {
    asm volatile("cp.async.cg.shared.global [%0], [%1], 16;" :: "r"(saddr), "l"(g));
}
__device__ __forceinline__ void ldsm4(uint32_t* r, uint32_t addr) {
    asm volatile("ldmatrix.sync.aligned.m8n8.x4.shared.b16 {%0,%1,%2,%3}, [%4];"
        : "=r"(r[0]), "=r"(r[1]), "=r"(r[2]), "=r"(r[3]) : "r"(addr));
}
__device__ __forceinline__ void mma_f16(float* c, const uint32_t* a, uint32_t b0, uint32_t b1) {
    asm volatile(
        "mma.sync.aligned.m16n8k16.row.col.f32.f16.f16.f32 "
        "{%0,%1,%2,%3}, {%4,%5,%6,%7}, {%8,%9}, {%0,%1,%2,%3};"
        : "+f"(c[0]), "+f"(c[1]), "+f"(c[2]), "+f"(c[3])
        : "r"(a[0]), "r"(a[1]), "r"(a[2]), "r"(a[3]), "r"(b0), "r"(b1));
}

// ---------------------------------------------------------------------------
// Kernel 1 (fused prep — R10 version, verified: ~20us, rel_err 2.2778e-4).
// fp32 row staging; transposed fp16 write of sqrt(w)*x.
// ---------------------------------------------------------------------------
extern __shared__ float psh[];

__global__ __launch_bounds__(256, 2)
void prep_kernel(const float* __restrict__ x) {
    float* wbuf = psh + 32 * PPAD;
    int b  = blockIdx.y;
    int l0 = blockIdx.x * 32;
    const float* __restrict__ Xb = x + ((size_t)b * LDIM + l0) * DDIM;
    int tid = threadIdx.x;
    int wid = tid >> 5, lane = tid & 31;

    #pragma unroll
    for (int rr = 0; rr < 4; rr++) {
        int r = wid * 4 + rr;
        const float4* Xr = (const float4*)(Xb + (size_t)r * DDIM);
        float* dr = psh + r * PPAD;
        float s = 0.f;
        #pragma unroll
        for (int i = 0; i < 6; i++) {
            float4 v = Xr[lane + i * 32];
            float* d = dr + (lane + i * 32) * 4;
            d[0] = v.x; d[1] = v.y; d[2] = v.z; d[3] = v.w;
            s = fmaf(v.x, v.x, s); s = fmaf(v.y, v.y, s);
            s = fmaf(v.z, v.z, s); s = fmaf(v.w, v.w, s);
        }
        #pragma unroll
        for (int o = 16; o > 0; o >>= 1) s += __shfl_xor_sync(0xffffffffu, s, o);
        if (lane == 0) wbuf[r] = sqrtf(sqrtf(EPSF + s));   // sqrt(w)
    }
    __syncthreads();

    int li8 = (lane & 3) * 8;
    int dof = lane >> 2;
    float sw[8];
    #pragma unroll
    for (int q = 0; q < 8; q++) sw[q] = wbuf[li8 + q];
    __half* __restrict__ Zb = g_Zh + (size_t)b * DDIM * LDIM + l0;

    #pragma unroll 4
    for (int it = 0; it < 12; it++) {
        int dd = it * 64 + wid * 8 + dof;
        __half2 h[4];
        #pragma unroll
        for (int q = 0; q < 4; q++) {
            float v0 = psh[(li8 + 2 * q)     * PPAD + dd] * sw[2 * q];
            float v1 = psh[(li8 + 2 * q + 1) * PPAD + dd] * sw[2 * q + 1];
            h[q] = __float22half2_rn(make_float2(v0, v1));
        }
        *(uint4*)(Zb + (size_t)dd * LDIM + li8) = *(uint4*)h;
    }
}

// ---------------------------------------------------------------------------
// Kernel 2: 128x64 C tile, 128 threads (2m x 2n warps, warp tile 64x32).
// BK=32 (64B rows, swizzle u^((row>>1)&3), verified in R9), 4 stages.
// Addresses collapsed to base+stride -> ~120 regs -> 4 CTAs/SM.
// ---------------------------------------------------------------------------
extern __shared__ char smc[];

__global__ __launch_bounds__(128, 4)
void gram_tc_kernel(float* __restrict__ C) {
    int p = blockIdx.x % NTILES;
    int b = blockIdx.x / NTILES;
    int ti = 0, rem = p;
    while (rem >= 12 - 2 * ti) { rem -= 12 - 2 * ti; ti++; }
    int tj = 2 * ti + rem;
    int m0 = ti * 128, n0 = tj * 64;

    const __half* __restrict__ Zb = g_Zh + (size_t)b * DDIM * LDIM;
    float* __restrict__ Cb = C + (size_t)b * DDIM * DDIM;

    int tid  = threadIdx.x;
    int wid  = tid >> 5, lane = tid & 31;
    int g = lane >> 2, t = lane & 3;
    int wm = (wid & 1) * 64;
    int wn = (wid >> 1) * 32;

    uint32_t sbase = (uint32_t)__cvta_generic_to_shared(smc);

    // cp.async bases: row0 = tid>>2 (0..31), u = tid&3; row_i = row0 + 32*i.
    // 32*i == 0 mod 4 on (row>>1)&3 -> swizzle invariant across i.
    int row0 = tid >> 2, u = tid & 3;
    uint32_t sw0 = ((u ^ ((row0 >> 1) & 3)) << 4);
    uint32_t sA0 = row0 * 64 + sw0;                        // + i*2048
    const __half* gA0 = Zb + (size_t)(m0 + row0) * LDIM + u * 8;   // + i*16384
    const __half* gB0 = Zb + (size_t)(n0 + row0) * LDIM + u * 8;

    auto ISSUE = [&](int chunk) {
        uint32_t base = sbase + (chunk & (STAGES - 1)) * STAGE_BYTES;
        int kc = chunk * BK;
        #pragma unroll
        for (int i = 0; i < 4; i++)
            cp16(base + sA0 + i * 2048, gA0 + kc + i * 16384);
        #pragma unroll
        for (int i = 0; i < 2; i++)
            cp16(base + A_BYTES + sA0 + i * 2048, gB0 + kc + i * 16384);
    };

    // ldmatrix row precompute (verified R9 lane algebra, 64B rows)
    int rowA[4], r3A[4];
    #pragma unroll
    for (int i = 0; i < 4; i++) {
        rowA[i] = wm + 16 * i + (lane & 7) + 8 * ((lane >> 3) & 1);
        r3A[i]  = (rowA[i] >> 1) & 3;
    }
    int uselA = lane >> 4;
    int rowB[2], r3B[2];
    #pragma unroll
    for (int jp = 0; jp < 2; jp++) {
        rowB[jp] = wn + 16 * jp + (lane & 7) + 8 * (lane >> 4);
        r3B[jp]  = (rowB[jp] >> 1) & 3;
    }
    int uselB = (lane >> 3) & 1;

    #pragma unroll
    for (int c = 0; c < STAGES - 1; c++) {
        ISSUE(c);
        asm volatile("cp.async.commit_group;" ::: "memory");
    }

    float acc[4][4][4];
    #pragma unroll
    for (int i = 0; i < 4; i++)
        #pragma unroll
        for (int j = 0; j < 4; j++)
            #pragma unroll
            for (int r = 0; r < 4; r++) acc[i][j][r] = 0.f;

    for (int c = 0; c < NCHUNK; c++) {
        asm volatile("cp.async.wait_group %0;" :: "n"(STAGES - 2) : "memory");
        __syncthreads();

        if (c + STAGES - 1 < NCHUNK) ISSUE(c + STAGES - 1);
        asm volatile("cp.async.commit_group;" ::: "memory");

        uint32_t Ab = sbase + (c & (STAGES - 1)) * STAGE_BYTES;
        uint32_t Bb = Ab + A_BYTES;

        #pragma unroll
        for (int ks = 0; ks < 2; ks++) {          // two k16 steps per BK=32
            int ku = ks * 2;
            uint32_t afr[4][4];
            #pragma unroll
            for (int i = 0; i < 4; i++)
                ldsm4(afr[i], Ab + rowA[i] * 64
                               + (((ku + uselA) ^ r3A[i]) << 4));
            uint32_t bfr[2][4];
            #pragma unroll
            for (int jp = 0; jp < 2; jp++)
                ldsm4(bfr[jp], Bb + rowB[jp] * 64
                                + (((ku + uselB) ^ r3B[jp]) << 4));
            #pragma unroll
            for (int i = 0; i < 4; i++)
                #pragma unroll
                for (int j = 0; j < 4; j++)
                    mma_f16(acc[i][j], afr[i],
                            bfr[j >> 1][(j & 1) * 2], bfr[j >> 1][(j & 1) * 2 + 1]);
        }
    }

    // Epilogue: direct tile
    #pragma unroll
    for (int i = 0; i < 4; i++) {
        #pragma unroll
        for (int j = 0; j < 4; j++) {
            int m = m0 + wm + 16 * i + g;
            int n = n0 + wn + 8 * j + 2 * t;
            *(float2*)(Cb + (size_t)m * DDIM + n) =
                make_float2(acc[i][j][0], acc[i][j][1]);
            *(float2*)(Cb + (size_t)(m + 8) * DDIM + n) =
                make_float2(acc[i][j][2], acc[i][j][3]);
        }
    }
    // Mirror (always; overlapping writes carry identical values)
    #pragma unroll
    for (int i = 0; i < 4; i++) {
        #pragma unroll
        for (int j = 0; j < 4; j++) {
            int m = m0 + wm + 16 * i + g;
            int n = n0 + wn + 8 * j + 2 * t;
            Cb[(size_t)n * DDIM + m]           = acc[i][j][0];
            Cb[(size_t)(n + 1) * DDIM + m]     = acc[i][j][1];
            Cb[(size_t)n * DDIM + m + 8]       = acc[i][j][2];
            Cb[(size_t)(n + 1) * DDIM + m + 8] = acc[i][j][3];
        }
    }
}

// ---------------------------------------------------------------------------
extern "C" void kernel_launch(void* const* d_in, const int* in_sizes, int n_in,
                              void* d_out, int out_size) {
    const float* x = (const float*)d_in[0];
    float* out = (float*)d_out;

    static int configured = 0;
    if (!configured) {
        cudaFuncSetAttribute(gram_tc_kernel,
                             cudaFuncAttributeMaxDynamicSharedMemorySize, SMEM_BYTES);
        cudaFuncSetAttribute(prep_kernel,
                             cudaFuncAttributeMaxDynamicSharedMemorySize, PREP_SMEM);
        configured = 1;
    }

    prep_kernel<<<dim3(LDIM / 32, BATCH), 256, PREP_SMEM>>>(x);
    gram_tc_kernel<<<BATCH * NTILES, 128, SMEM_BYTES>>>(out);
}